// round 15
// baseline (speedup 1.0000x reference)
#include <cuda_runtime.h>
#include <cuda_bf16.h>
#include <math.h>
#include <stdint.h>

// Problem constants
#define HIDDEN 1024
#define FEAT   2048
#define KB     512      // BOTTLENECK
#define BATCH  64
#define TT     512      // T
#define BT     (BATCH*TT)   // 32768

// GEMM tiling
#define BM 128
#define BN 256
#define BK 32                    // bf16 elems per chunk (64B rows)
#define NCHUNK (FEAT / BK)       // 64
#define STAGE_BYTES 49152        // Ahi 8K + Alo 8K + Bhi 16K + Blo 16K
#define OFF_AHI 0
#define OFF_ALO 8192
#define OFF_BHI 16384
#define OFF_BLO 32768
#define OFF_WHB (2 * STAGE_BYTES)          // 98304
#define OFF_WV  (OFF_WHB + 1024)           // 99328
#define OFF_RED (OFF_WV + 1024)            // 100352
#define SMEM_TOTAL (OFF_RED + 2048)        // 102400

// ---------------------------------------------------------------------------
// Device scratch (no allocations allowed)
// ---------------------------------------------------------------------------
__device__ float g_Wh[BATCH * KB];
__device__ float g_epart[2 * BT];
__device__ float g_weights[BT];
__device__ __nv_bfloat16 g_fhi[(size_t)BT * FEAT];   // 128MB
__device__ __nv_bfloat16 g_flo[(size_t)BT * FEAT];   // 128MB
__device__ __nv_bfloat16 g_uhi[KB * FEAT];
__device__ __nv_bfloat16 g_ulo[KB * FEAT];

// ---------------------------------------------------------------------------
// PTX helpers (base-target safe: mma.sync / ldmatrix / cp.async only)
// ---------------------------------------------------------------------------
__device__ __forceinline__ uint32_t smem_to_u32(const void* p) {
    uint32_t a;
    asm("{ .reg .u64 t; cvta.to.shared.u64 t, %1; cvt.u32.u64 %0, t; }" : "=r"(a) : "l"(p));
    return a;
}
__device__ __forceinline__ void cpa16(uint32_t d, const void* s) {
    asm volatile("cp.async.cg.shared.global [%0], [%1], 16;" :: "r"(d), "l"(s));
}
__device__ __forceinline__ void ldsm4(uint32_t* r, uint32_t addr) {
    asm volatile("ldmatrix.sync.aligned.m8n8.x4.shared.b16 {%0,%1,%2,%3}, [%4];"
        : "=r"(r[0]), "=r"(r[1]), "=r"(r[2]), "=r"(r[3]) : "r"(addr));
}
__device__ __forceinline__ void mma16816(float* c, const uint32_t* a,
                                         uint32_t b0, uint32_t b1) {
    asm volatile(
        "mma.sync.aligned.m16n8k16.row.col.f32.bf16.bf16.f32 "
        "{%0,%1,%2,%3}, {%4,%5,%6,%7}, {%8,%9}, {%0,%1,%2,%3};"
        : "+f"(c[0]), "+f"(c[1]), "+f"(c[2]), "+f"(c[3])
        : "r"(a[0]), "r"(a[1]), "r"(a[2]), "r"(a[3]), "r"(b0), "r"(b1));
}

// ---------------------------------------------------------------------------
// Conversion kernels: fp32 -> (bf16 hi, bf16 lo)
// ---------------------------------------------------------------------------
__device__ __forceinline__ uint32_t pack_bf2(__nv_bfloat16 a, __nv_bfloat16 b) {
    return (uint32_t)__bfloat16_as_ushort(a) | ((uint32_t)__bfloat16_as_ushort(b) << 16);
}
__device__ __forceinline__ void split4(float4 v, uint32_t* hi, uint32_t* lo) {
    float x[4] = {v.x, v.y, v.z, v.w};
    __nv_bfloat16 h[4], l[4];
#pragma unroll
    for (int j = 0; j < 4; j++) {
        h[j] = __float2bfloat16_rn(x[j]);
        l[j] = __float2bfloat16_rn(x[j] - __bfloat162float(h[j]));
    }
    hi[0] = pack_bf2(h[0], h[1]); hi[1] = pack_bf2(h[2], h[3]);
    lo[0] = pack_bf2(l[0], l[1]); lo[1] = pack_bf2(l[2], l[3]);
}
__global__ void cvt_feats_kernel(const float* __restrict__ src) {
    size_t i = (size_t)blockIdx.x * blockDim.x + threadIdx.x;  // float4 index
    float4 v = ((const float4*)src)[i];
    uint32_t hi[2], lo[2];
    split4(v, hi, lo);
    ((uint32_t*)g_fhi)[2 * i]     = hi[0];
    ((uint32_t*)g_fhi)[2 * i + 1] = hi[1];
    ((uint32_t*)g_flo)[2 * i]     = lo[0];
    ((uint32_t*)g_flo)[2 * i + 1] = lo[1];
}
__global__ void cvt_u_kernel(const float* __restrict__ src) {
    size_t i = (size_t)blockIdx.x * blockDim.x + threadIdx.x;
    float4 v = ((const float4*)src)[i];
    uint32_t hi[2], lo[2];
    split4(v, hi, lo);
    ((uint32_t*)g_uhi)[2 * i]     = hi[0];
    ((uint32_t*)g_uhi)[2 * i + 1] = hi[1];
    ((uint32_t*)g_ulo)[2 * i]     = lo[0];
    ((uint32_t*)g_ulo)[2 * i + 1] = lo[1];
}

// ---------------------------------------------------------------------------
// Wh[b,k] = hidden[b,:] . W[k,:]  (fp32, tiny)
// ---------------------------------------------------------------------------
__global__ void wh_kernel(const float* __restrict__ hidden,
                          const float* __restrict__ W) {
    int b = blockIdx.x;
    int k = blockIdx.y * 128 + threadIdx.x;
    __shared__ __align__(16) float4 hs[HIDDEN / 4];
    const float4* hv = (const float4*)(hidden + (size_t)b * HIDDEN);
    for (int i = threadIdx.x; i < HIDDEN / 4; i += 128) hs[i] = hv[i];
    __syncthreads();
    const float4* Wr = (const float4*)(W + (size_t)k * HIDDEN);
    float s = 0.0f;
#pragma unroll 8
    for (int i = 0; i < HIDDEN / 4; i++) {
        float4 a = hs[i], v = Wr[i];
        s += a.x * v.x + a.y * v.y + a.z * v.z + a.w * v.w;
    }
    g_Wh[b * KB + k] = s;
}

// ---------------------------------------------------------------------------
// Energies GEMM via mma.sync bf16 (3-product fp32-emulation) + fused epilogue.
// grid (2, 256): x = N half (col0 = x*256), y = M tile (row0 = y*128).
// 512 threads = 16 warps (4 M x 4 N), warp tile 32x64.
// ---------------------------------------------------------------------------
__global__ __launch_bounds__(512, 1) void energies_mma_kernel(
    const float* __restrict__ bias, const float* __restrict__ wvec) {
    extern __shared__ char smem[];
    const uint32_t sb = smem_to_u32(smem);
    const int tid = threadIdx.x;
    const int lane = tid & 31, warp = tid >> 5;
    const int warp_m = warp & 3, warp_n = warp >> 2;
    const int nhalf = blockIdx.x, mtile = blockIdx.y;
    const int row0 = mtile * BM, col0 = nhalf * BN;
    const int b = row0 >> 9;

    float* whb = (float*)(smem + OFF_WHB);
    float* wv  = (float*)(smem + OFF_WV);
    float* red = (float*)(smem + OFF_RED);

    if (tid < 256) {
        int k = col0 + tid;
        whb[tid] = g_Wh[b * KB + k] + bias[k];
        wv[tid] = wvec[k];
    }

    float acc[2][8][4];
#pragma unroll
    for (int mt = 0; mt < 2; mt++)
#pragma unroll
        for (int nt = 0; nt < 8; nt++)
#pragma unroll
            for (int j = 0; j < 4; j++) acc[mt][nt][j] = 0.0f;

    const __nv_bfloat16* fh = g_fhi + (size_t)row0 * FEAT;
    const __nv_bfloat16* fl = g_flo + (size_t)row0 * FEAT;
    const __nv_bfloat16* uh = g_uhi + (size_t)col0 * FEAT;
    const __nv_bfloat16* ul = g_ulo + (size_t)col0 * FEAT;

    // cp.async destination swizzle:  phys(row, c) = row*64 + ((c ^ ((row>>1)&3))*16)
    const int arow = tid >> 2, ac = tid & 3;
    const uint32_t a_dst = arow * 64 + ((ac ^ ((arow >> 1) & 3)) * 16);
    const int brow0 = tid >> 2, brow1 = brow0 + 128, bc = tid & 3;
    const uint32_t b_dst0 = brow0 * 64 + ((bc ^ ((brow0 >> 1) & 3)) * 16);
    const uint32_t b_dst1 = brow1 * 64 + ((bc ^ ((brow1 >> 1) & 3)) * 16);

    // ldmatrix address components
    const int sub = lane >> 3, l7 = lane & 7;
    const int a_rb = warp_m * 32 + (sub & 1) * 8 + l7;  // + mt*16
    const int a_c0 = sub >> 1;
    const int b_nb = warp_n * 64 + (sub >> 1) * 8 + l7; // + np*16
    const int b_c0 = sub & 1;

#define LOAD_CHUNK(stage, kc) do {                                            \
    uint32_t st_ = sb + (stage) * STAGE_BYTES;                                \
    size_t fo_ = (size_t)(kc) * BK + ac * 8;                                  \
    cpa16(st_ + OFF_AHI + a_dst, fh + (size_t)arow * FEAT + fo_);             \
    cpa16(st_ + OFF_ALO + a_dst, fl + (size_t)arow * FEAT + fo_);             \
    size_t bo_ = (size_t)(kc) * BK + bc * 8;                                  \
    cpa16(st_ + OFF_BHI + b_dst0, uh + (size_t)brow0 * FEAT + bo_);           \
    cpa16(st_ + OFF_BHI + b_dst1, uh + (size_t)brow1 * FEAT + bo_);           \
    cpa16(st_ + OFF_BLO + b_dst0, ul + (size_t)brow0 * FEAT + bo_);           \
    cpa16(st_ + OFF_BLO + b_dst1, ul + (size_t)brow1 * FEAT + bo_);           \
    asm volatile("cp.async.commit_group;" ::: "memory");                      \
} while (0)

    LOAD_CHUNK(0, 0);

    for (int kc = 0; kc < NCHUNK; kc++) {
        const int cur = kc & 1;
        if (kc + 1 < NCHUNK) {
            LOAD_CHUNK(cur ^ 1, kc + 1);
            asm volatile("cp.async.wait_group 1;" ::: "memory");
        } else {
            asm volatile("cp.async.wait_group 0;" ::: "memory");
        }
        __syncthreads();

        const uint32_t st = sb + cur * STAGE_BYTES;
#pragma unroll
        for (int k16 = 0; k16 < 2; k16++) {
            uint32_t ah[2][4], al[2][4];
#pragma unroll
            for (int mt = 0; mt < 2; mt++) {
                int row = a_rb + mt * 16;
                uint32_t aoff = row * 64 + (((k16 * 2 + a_c0) ^ ((row >> 1) & 3)) * 16);
                ldsm4(ah[mt], st + OFF_AHI + aoff);
                ldsm4(al[mt], st + OFF_ALO + aoff);
            }
#pragma unroll
            for (int np = 0; np < 4; np++) {
                int nrow = b_nb + np * 16;
                uint32_t boff = nrow * 64 + (((k16 * 2 + b_c0) ^ ((nrow >> 1) & 3)) * 16);
                uint32_t bh[4], bl[4];
                ldsm4(bh, st + OFF_BHI + boff);
                ldsm4(bl, st + OFF_BLO + boff);
#pragma unroll
                for (int mt = 0; mt < 2; mt++) {
                    mma16816(acc[mt][np * 2 + 0], ah[mt], bh[0], bh[1]);
                    mma16816(acc[mt][np * 2 + 0], ah[mt], bl[0], bl[1]);
                    mma16816(acc[mt][np * 2 + 0], al[mt], bh[0], bh[1]);
                    mma16816(acc[mt][np * 2 + 1], ah[mt], bh[2], bh[3]);
                    mma16816(acc[mt][np * 2 + 1], ah[mt], bl[2], bl[3]);
                    mma16816(acc[mt][np * 2 + 1], al[mt], bh[2], bh[3]);
                }
            }
        }
        __syncthreads();
    }

    // Epilogue: per-thread tanh + w-dot over owned cols, reduce to per-row.
    const int g = lane >> 2, t4 = lane & 3;
#pragma unroll
    for (int mt = 0; mt < 2; mt++) {
#pragma unroll
        for (int half = 0; half < 2; half++) {
            int ml = warp_m * 32 + mt * 16 + half * 8 + g;
            float p = 0.0f;
#pragma unroll
            for (int nt = 0; nt < 8; nt++) {
#pragma unroll
                for (int j = 0; j < 2; j++) {
                    int col = warp_n * 64 + nt * 8 + t4 * 2 + j;
                    p += wv[col] * tanhf(acc[mt][nt][half * 2 + j] + whb[col]);
                }
            }
            p += __shfl_xor_sync(0xffffffffu, p, 1);
            p += __shfl_xor_sync(0xffffffffu, p, 2);
            if (t4 == 0) red[warp_n * 128 + ml] = p;
        }
    }
    __syncthreads();
    if (tid < 128) {
        float s = red[tid] + red[128 + tid] + red[256 + tid] + red[384 + tid];
        g_epart[(size_t)nhalf * BT + row0 + tid] = s;
    }
}

// ---------------------------------------------------------------------------
// Softmax over T per batch (sums the 2 N-half partials)
// ---------------------------------------------------------------------------
__global__ void softmax_kernel(float* __restrict__ wout) {
    int b = blockIdx.x;
    int t = threadIdx.x;
    float e = g_epart[b * TT + t] + g_epart[(size_t)BT + b * TT + t];

    __shared__ float sm[16];
    float m = e;
#pragma unroll
    for (int o = 16; o > 0; o >>= 1) m = fmaxf(m, __shfl_xor_sync(0xffffffffu, m, o));
    if ((t & 31) == 0) sm[t >> 5] = m;
    __syncthreads();
    if (t < 16) {
        float mm = sm[t];
#pragma unroll
        for (int o = 8; o > 0; o >>= 1) mm = fmaxf(mm, __shfl_xor_sync(0xffffu, mm, o));
        if (t == 0) sm[0] = mm;
    }
    __syncthreads();
    m = sm[0];
    __syncthreads();

    float ex = expf(e - m);
    float s = ex;
#pragma unroll
    for (int o = 16; o > 0; o >>= 1) s += __shfl_xor_sync(0xffffffffu, s, o);
    if ((t & 31) == 0) sm[t >> 5] = s;
    __syncthreads();
    if (t < 16) {
        float ss = sm[t];
#pragma unroll
        for (int o = 8; o > 0; o >>= 1) ss += __shfl_xor_sync(0xffffu, ss, o);
        if (t == 0) sm[0] = ss;
    }
    __syncthreads();
    float inv = 1.0f / sm[0];

    float wgt = ex * inv;
    g_weights[b * TT + t] = wgt;
    wout[b * TT + t] = wgt;
}

// ---------------------------------------------------------------------------
// attn_feats[b,f] = sum_t feats[b,t,f] * weights[b,t]   (DRAM-bound)
// ---------------------------------------------------------------------------
__global__ void attn_kernel(const float* __restrict__ feats,
                            float* __restrict__ out) {
    int b = blockIdx.x;
    int f = blockIdx.y * 256 + threadIdx.x;
    __shared__ float ws[TT];
    for (int i = threadIdx.x; i < TT; i += 256) ws[i] = g_weights[b * TT + i];
    __syncthreads();
    const float* fb = feats + (size_t)b * TT * FEAT + f;
    float acc = 0.0f;
#pragma unroll 8
    for (int t = 0; t < TT; t++) acc += fb[(size_t)t * FEAT] * ws[t];
    out[(size_t)b * FEAT + f] = acc;
}

// ---------------------------------------------------------------------------
extern "C" void kernel_launch(void* const* d_in, const int* in_sizes, int n_in,
                              void* d_out, int out_size) {
    const float* hidden = (const float*)d_in[0];  // [64,1024]
    const float* feats  = (const float*)d_in[1];  // [64,512,2048]
    const float* W      = (const float*)d_in[2];  // [512,1024]
    const float* U      = (const float*)d_in[3];  // [512,2048]
    const float* bias   = (const float*)d_in[4];  // [512]
    const float* w      = (const float*)d_in[5];  // [1,512]
    float* out = (float*)d_out;                   // [attn 64*2048 | weights 64*512]

    cudaFuncSetAttribute(energies_mma_kernel,
                         cudaFuncAttributeMaxDynamicSharedMemorySize, SMEM_TOTAL);

    cvt_feats_kernel<<<(BT * (FEAT / 4)) / 256, 256>>>(feats);
    cvt_u_kernel<<<(KB * (FEAT / 4)) / 256, 256>>>(U);
    wh_kernel<<<dim3(64, 4), 128>>>(hidden, W);
    energies_mma_kernel<<<dim3(2, 256), 512, SMEM_TOTAL>>>(bias, w);
    softmax_kernel<<<64, 512>>>(out + (size_t)BATCH * FEAT);
    attn_kernel<<<dim3(64, 8), 256>>>(feats, out);
}

// round 16
// speedup vs baseline: 1.0022x; 1.0022x over previous
#include <cuda_runtime.h>
#include <cuda_bf16.h>
#include <math.h>
#include <stdint.h>

// Problem constants
#define HIDDEN 1024
#define FEAT   2048
#define KB     512      // BOTTLENECK
#define BATCH  64
#define TT     512      // T
#define BT     (BATCH*TT)   // 32768

// GEMM tiling
#define BM 128
#define BN 256
#define BK 32                    // bf16 elems per chunk (64B rows)
#define NCHUNK (FEAT / BK)       // 64
#define STAGE_BYTES 49152        // Ahi 8K + Alo 8K + Bhi 16K + Blo 16K
#define OFF_AHI 0
#define OFF_ALO 8192
#define OFF_BHI 16384
#define OFF_BLO 32768
#define OFF_WHB (2 * STAGE_BYTES)          // 98304
#define OFF_WV  (OFF_WHB + 1024)           // 99328
#define OFF_RED (OFF_WV + 1024)            // 100352
#define SMEM_TOTAL (OFF_RED + 2048)        // 102400

// ---------------------------------------------------------------------------
// Device scratch (no allocations allowed)
// ---------------------------------------------------------------------------
__device__ float g_Wh[BATCH * KB];
__device__ float g_epart[2 * BT];
__device__ float g_weights[BT];
__device__ __nv_bfloat16 g_fhi[(size_t)BT * FEAT];   // 128MB
__device__ __nv_bfloat16 g_flo[(size_t)BT * FEAT];   // 128MB
__device__ __nv_bfloat16 g_uhi[KB * FEAT];
__device__ __nv_bfloat16 g_ulo[KB * FEAT];

// ---------------------------------------------------------------------------
// PTX helpers (base-target safe: mma.sync / ldmatrix / cp.async only)
// ---------------------------------------------------------------------------
__device__ __forceinline__ uint32_t smem_to_u32(const void* p) {
    uint32_t a;
    asm("{ .reg .u64 t; cvta.to.shared.u64 t, %1; cvt.u32.u64 %0, t; }" : "=r"(a) : "l"(p));
    return a;
}
__device__ __forceinline__ void cpa16(uint32_t d, const void* s) {
    asm volatile("cp.async.cg.shared.global [%0], [%1], 16;" :: "r"(d), "l"(s));
}
__device__ __forceinline__ void ldsm4(uint32_t* r, uint32_t addr) {
    asm volatile("ldmatrix.sync.aligned.m8n8.x4.shared.b16 {%0,%1,%2,%3}, [%4];"
        : "=r"(r[0]), "=r"(r[1]), "=r"(r[2]), "=r"(r[3]) : "r"(addr));
}
__device__ __forceinline__ void mma16816(float* c, const uint32_t* a,
                                         uint32_t b0, uint32_t b1) {
    asm volatile(
        "mma.sync.aligned.m16n8k16.row.col.f32.bf16.bf16.f32 "
        "{%0,%1,%2,%3}, {%4,%5,%6,%7}, {%8,%9}, {%0,%1,%2,%3};"
        : "+f"(c[0]), "+f"(c[1]), "+f"(c[2]), "+f"(c[3])
        : "r"(a[0]), "r"(a[1]), "r"(a[2]), "r"(a[3]), "r"(b0), "r"(b1));
}

// ---------------------------------------------------------------------------
// Conversion kernels: fp32 -> (bf16 hi, bf16 lo)
// ---------------------------------------------------------------------------
__device__ __forceinline__ uint32_t pack_bf2(__nv_bfloat16 a, __nv_bfloat16 b) {
    return (uint32_t)__bfloat16_as_ushort(a) | ((uint32_t)__bfloat16_as_ushort(b) << 16);
}
__device__ __forceinline__ void split4(float4 v, uint32_t* hi, uint32_t* lo) {
    float x[4] = {v.x, v.y, v.z, v.w};
    __nv_bfloat16 h[4], l[4];
#pragma unroll
    for (int j = 0; j < 4; j++) {
        h[j] = __float2bfloat16_rn(x[j]);
        l[j] = __float2bfloat16_rn(x[j] - __bfloat162float(h[j]));
    }
    hi[0] = pack_bf2(h[0], h[1]); hi[1] = pack_bf2(h[2], h[3]);
    lo[0] = pack_bf2(l[0], l[1]); lo[1] = pack_bf2(l[2], l[3]);
}
__global__ void cvt_feats_kernel(const float* __restrict__ src) {
    size_t i = (size_t)blockIdx.x * blockDim.x + threadIdx.x;  // float4 index
    float4 v = ((const float4*)src)[i];
    uint32_t hi[2], lo[2];
    split4(v, hi, lo);
    ((uint32_t*)g_fhi)[2 * i]     = hi[0];
    ((uint32_t*)g_fhi)[2 * i + 1] = hi[1];
    ((uint32_t*)g_flo)[2 * i]     = lo[0];
    ((uint32_t*)g_flo)[2 * i + 1] = lo[1];
}
__global__ void cvt_u_kernel(const float* __restrict__ src) {
    size_t i = (size_t)blockIdx.x * blockDim.x + threadIdx.x;
    float4 v = ((const float4*)src)[i];
    uint32_t hi[2], lo[2];
    split4(v, hi, lo);
    ((uint32_t*)g_uhi)[2 * i]     = hi[0];
    ((uint32_t*)g_uhi)[2 * i + 1] = hi[1];
    ((uint32_t*)g_ulo)[2 * i]     = lo[0];
    ((uint32_t*)g_ulo)[2 * i + 1] = lo[1];
}

// ---------------------------------------------------------------------------
// Wh[b,k] = hidden[b,:] . W[k,:]  (fp32, tiny)
// ---------------------------------------------------------------------------
__global__ void wh_kernel(const float* __restrict__ hidden,
                          const float* __restrict__ W) {
    int b = blockIdx.x;
    int k = blockIdx.y * 128 + threadIdx.x;
    __shared__ __align__(16) float4 hs[HIDDEN / 4];
    const float4* hv = (const float4*)(hidden + (size_t)b * HIDDEN);
    for (int i = threadIdx.x; i < HIDDEN / 4; i += 128) hs[i] = hv[i];
    __syncthreads();
    const float4* Wr = (const float4*)(W + (size_t)k * HIDDEN);
    float s = 0.0f;
#pragma unroll 8
    for (int i = 0; i < HIDDEN / 4; i++) {
        float4 a = hs[i], v = Wr[i];
        s += a.x * v.x + a.y * v.y + a.z * v.z + a.w * v.w;
    }
    g_Wh[b * KB + k] = s;
}

// ---------------------------------------------------------------------------
// Energies GEMM via mma.sync bf16 (3-product fp32-emulation) + fused epilogue.
// grid (2, 256): x = N half (col0 = x*256), y = M tile (row0 = y*128).
// 512 threads = 16 warps (4 M x 4 N), warp tile 32x64.
// ---------------------------------------------------------------------------
__global__ __launch_bounds__(512, 1) void energies_mma_kernel(
    const float* __restrict__ bias, const float* __restrict__ wvec) {
    extern __shared__ char smem[];
    const uint32_t sb = smem_to_u32(smem);
    const int tid = threadIdx.x;
    const int lane = tid & 31, warp = tid >> 5;
    const int warp_m = warp & 3, warp_n = warp >> 2;
    const int nhalf = blockIdx.x, mtile = blockIdx.y;
    const int row0 = mtile * BM, col0 = nhalf * BN;
    const int b = row0 >> 9;

    float* whb = (float*)(smem + OFF_WHB);
    float* wv  = (float*)(smem + OFF_WV);
    float* red = (float*)(smem + OFF_RED);

    if (tid < 256) {
        int k = col0 + tid;
        whb[tid] = g_Wh[b * KB + k] + bias[k];
        wv[tid] = wvec[k];
    }

    float acc[2][8][4];
#pragma unroll
    for (int mt = 0; mt < 2; mt++)
#pragma unroll
        for (int nt = 0; nt < 8; nt++)
#pragma unroll
            for (int j = 0; j < 4; j++) acc[mt][nt][j] = 0.0f;

    const __nv_bfloat16* fh = g_fhi + (size_t)row0 * FEAT;
    const __nv_bfloat16* fl = g_flo + (size_t)row0 * FEAT;
    const __nv_bfloat16* uh = g_uhi + (size_t)col0 * FEAT;
    const __nv_bfloat16* ul = g_ulo + (size_t)col0 * FEAT;

    // cp.async destination swizzle:  phys(row, c) = row*64 + ((c ^ ((row>>1)&3))*16)
    const int arow = tid >> 2, ac = tid & 3;
    const uint32_t a_dst = arow * 64 + ((ac ^ ((arow >> 1) & 3)) * 16);
    const int brow0 = tid >> 2, brow1 = brow0 + 128, bc = tid & 3;
    const uint32_t b_dst0 = brow0 * 64 + ((bc ^ ((brow0 >> 1) & 3)) * 16);
    const uint32_t b_dst1 = brow1 * 64 + ((bc ^ ((brow1 >> 1) & 3)) * 16);

    // ldmatrix address components
    const int sub = lane >> 3, l7 = lane & 7;
    const int a_rb = warp_m * 32 + (sub & 1) * 8 + l7;  // + mt*16
    const int a_c0 = sub >> 1;
    const int b_nb = warp_n * 64 + (sub >> 1) * 8 + l7; // + np*16
    const int b_c0 = sub & 1;

#define LOAD_CHUNK(stage, kc) do {                                            \
    uint32_t st_ = sb + (stage) * STAGE_BYTES;                                \
    size_t fo_ = (size_t)(kc) * BK + ac * 8;                                  \
    cpa16(st_ + OFF_AHI + a_dst, fh + (size_t)arow * FEAT + fo_);             \
    cpa16(st_ + OFF_ALO + a_dst, fl + (size_t)arow * FEAT + fo_);             \
    size_t bo_ = (size_t)(kc) * BK + bc * 8;                                  \
    cpa16(st_ + OFF_BHI + b_dst0, uh + (size_t)brow0 * FEAT + bo_);           \
    cpa16(st_ + OFF_BHI + b_dst1, uh + (size_t)brow1 * FEAT + bo_);           \
    cpa16(st_ + OFF_BLO + b_dst0, ul + (size_t)brow0 * FEAT + bo_);           \
    cpa16(st_ + OFF_BLO + b_dst1, ul + (size_t)brow1 * FEAT + bo_);           \
    asm volatile("cp.async.commit_group;" ::: "memory");                      \
} while (0)

    LOAD_CHUNK(0, 0);

    for (int kc = 0; kc < NCHUNK; kc++) {
        const int cur = kc & 1;
        if (kc + 1 < NCHUNK) {
            LOAD_CHUNK(cur ^ 1, kc + 1);
            asm volatile("cp.async.wait_group 1;" ::: "memory");
        } else {
            asm volatile("cp.async.wait_group 0;" ::: "memory");
        }
        __syncthreads();

        const uint32_t st = sb + cur * STAGE_BYTES;
#pragma unroll
        for (int k16 = 0; k16 < 2; k16++) {
            uint32_t ah[2][4], al[2][4];
#pragma unroll
            for (int mt = 0; mt < 2; mt++) {
                int row = a_rb + mt * 16;
                uint32_t aoff = row * 64 + (((k16 * 2 + a_c0) ^ ((row >> 1) & 3)) * 16);
                ldsm4(ah[mt], st + OFF_AHI + aoff);
                ldsm4(al[mt], st + OFF_ALO + aoff);
            }
#pragma unroll
            for (int np = 0; np < 4; np++) {
                int nrow = b_nb + np * 16;
                uint32_t boff = nrow * 64 + (((k16 * 2 + b_c0) ^ ((nrow >> 1) & 3)) * 16);
                uint32_t bh[4], bl[4];
                ldsm4(bh, st + OFF_BHI + boff);
                ldsm4(bl, st + OFF_BLO + boff);
#pragma unroll
                for (int mt = 0; mt < 2; mt++) {
                    mma16816(acc[mt][np * 2 + 0], ah[mt], bh[0], bh[1]);
                    mma16816(acc[mt][np * 2 + 0], ah[mt], bl[0], bl[1]);
                    mma16816(acc[mt][np * 2 + 0], al[mt], bh[0], bh[1]);
                    mma16816(acc[mt][np * 2 + 1], ah[mt], bh[2], bh[3]);
                    mma16816(acc[mt][np * 2 + 1], ah[mt], bl[2], bl[3]);
                    mma16816(acc[mt][np * 2 + 1], al[mt], bh[2], bh[3]);
                }
            }
        }
        __syncthreads();
    }

    // Epilogue: per-thread tanh + w-dot over owned cols, reduce to per-row.
    const int g = lane >> 2, t4 = lane & 3;
#pragma unroll
    for (int mt = 0; mt < 2; mt++) {
#pragma unroll
        for (int half = 0; half < 2; half++) {
            int ml = warp_m * 32 + mt * 16 + half * 8 + g;
            float p = 0.0f;
#pragma unroll
            for (int nt = 0; nt < 8; nt++) {
#pragma unroll
                for (int j = 0; j < 2; j++) {
                    int col = warp_n * 64 + nt * 8 + t4 * 2 + j;
                    p += wv[col] * tanhf(acc[mt][nt][half * 2 + j] + whb[col]);
                }
            }
            p += __shfl_xor_sync(0xffffffffu, p, 1);
            p += __shfl_xor_sync(0xffffffffu, p, 2);
            if (t4 == 0) red[warp_n * 128 + ml] = p;
        }
    }
    __syncthreads();
    if (tid < 128) {
        float s = red[tid] + red[128 + tid] + red[256 + tid] + red[384 + tid];
        g_epart[(size_t)nhalf * BT + row0 + tid] = s;
    }
}

// ---------------------------------------------------------------------------
// Softmax over T per batch (sums the 2 N-half partials)
// ---------------------------------------------------------------------------
__global__ void softmax_kernel(float* __restrict__ wout) {
    int b = blockIdx.x;
    int t = threadIdx.x;
    float e = g_epart[b * TT + t] + g_epart[(size_t)BT + b * TT + t];

    __shared__ float sm[16];
    float m = e;
#pragma unroll
    for (int o = 16; o > 0; o >>= 1) m = fmaxf(m, __shfl_xor_sync(0xffffffffu, m, o));
    if ((t & 31) == 0) sm[t >> 5] = m;
    __syncthreads();
    if (t < 16) {
        float mm = sm[t];
#pragma unroll
        for (int o = 8; o > 0; o >>= 1) mm = fmaxf(mm, __shfl_xor_sync(0xffffu, mm, o));
        if (t == 0) sm[0] = mm;
    }
    __syncthreads();
    m = sm[0];
    __syncthreads();

    float ex = expf(e - m);
    float s = ex;
#pragma unroll
    for (int o = 16; o > 0; o >>= 1) s += __shfl_xor_sync(0xffffffffu, s, o);
    if ((t & 31) == 0) sm[t >> 5] = s;
    __syncthreads();
    if (t < 16) {
        float ss = sm[t];
#pragma unroll
        for (int o = 8; o > 0; o >>= 1) ss += __shfl_xor_sync(0xffffu, ss, o);
        if (t == 0) sm[0] = ss;
    }
    __syncthreads();
    float inv = 1.0f / sm[0];

    float wgt = ex * inv;
    g_weights[b * TT + t] = wgt;
    wout[b * TT + t] = wgt;
}

// ---------------------------------------------------------------------------
// attn_feats[b,f] = sum_t feats[b,t,f] * weights[b,t]   (DRAM-bound)
// ---------------------------------------------------------------------------
__global__ void attn_kernel(const float* __restrict__ feats,
                            float* __restrict__ out) {
    int b = blockIdx.x;
    int f = blockIdx.y * 256 + threadIdx.x;
    __shared__ float ws[TT];
    for (int i = threadIdx.x; i < TT; i += 256) ws[i] = g_weights[b * TT + i];
    __syncthreads();
    const float* fb = feats + (size_t)b * TT * FEAT + f;
    float acc = 0.0f;
#pragma unroll 8
    for (int t = 0; t < TT; t++) acc += fb[(size_t)t * FEAT] * ws[t];
    out[(size_t)b * FEAT + f] = acc;
}

// ---------------------------------------------------------------------------
extern "C" void kernel_launch(void* const* d_in, const int* in_sizes, int n_in,
                              void* d_out, int out_size) {
    const float* hidden = (const float*)d_in[0];  // [64,1024]
    const float* feats  = (const float*)d_in[1];  // [64,512,2048]
    const float* W      = (const float*)d_in[2];  // [512,1024]
    const float* U      = (const float*)d_in[3];  // [512,2048]
    const float* bias   = (const float*)d_in[4];  // [512]
    const float* w      = (const float*)d_in[5];  // [1,512]
    float* out = (float*)d_out;                   // [attn 64*2048 | weights 64*512]

    cudaFuncSetAttribute(energies_mma_kernel,
                         cudaFuncAttributeMaxDynamicSharedMemorySize, SMEM_TOTAL);

    cvt_feats_kernel<<<(BT * (FEAT / 4)) / 256, 256>>>(feats);
    cvt_u_kernel<<<(KB * (FEAT / 4)) / 256, 256>>>(U);
    wh_kernel<<<dim3(64, 4), 128>>>(hidden, W);
    energies_mma_kernel<<<dim3(2, 256), 512, SMEM_TOTAL>>>(bias, w);
    softmax_kernel<<<64, 512>>>(out + (size_t)BATCH * FEAT);
    attn_kernel<<<dim3(64, 8), 256>>>(feats, out);
}

// round 17
// speedup vs baseline: 1.0051x; 1.0029x over previous
#include <cuda_runtime.h>
#include <cuda_bf16.h>
#include <math.h>
#include <stdint.h>

// Problem constants
#define HIDDEN 1024
#define FEAT   2048
#define KB     512      // BOTTLENECK
#define BATCH  64
#define TT     512      // T
#define BT     (BATCH*TT)   // 32768

// GEMM tiling
#define BM 128
#define BN 256
#define BK 32                    // bf16 elems per chunk (64B rows)
#define NCHUNK (FEAT / BK)       // 64
#define STAGE_BYTES 49152        // Ahi 8K + Alo 8K + Bhi 16K + Blo 16K
#define OFF_AHI 0
#define OFF_ALO 8192
#define OFF_BHI 16384
#define OFF_BLO 32768
#define OFF_WHB (2 * STAGE_BYTES)          // 98304
#define OFF_WV  (OFF_WHB + 1024)           // 99328
#define OFF_RED (OFF_WV + 1024)            // 100352
#define SMEM_TOTAL (OFF_RED + 2048)        // 102400

// ---------------------------------------------------------------------------
// Device scratch (no allocations allowed)
// ---------------------------------------------------------------------------
__device__ float g_Wh[BATCH * KB];
__device__ float g_epart[2 * BT];
__device__ float g_weights[BT];
__device__ __nv_bfloat16 g_fhi[(size_t)BT * FEAT];   // 128MB
__device__ __nv_bfloat16 g_flo[(size_t)BT * FEAT];   // 128MB
__device__ __nv_bfloat16 g_uhi[KB * FEAT];
__device__ __nv_bfloat16 g_ulo[KB * FEAT];

// ---------------------------------------------------------------------------
// PTX helpers (base-target safe: mma.sync / ldmatrix / cp.async only)
// ---------------------------------------------------------------------------
__device__ __forceinline__ uint32_t smem_to_u32(const void* p) {
    uint32_t a;
    asm("{ .reg .u64 t; cvta.to.shared.u64 t, %1; cvt.u32.u64 %0, t; }" : "=r"(a) : "l"(p));
    return a;
}
__device__ __forceinline__ void cpa16(uint32_t d, const void* s) {
    asm volatile("cp.async.cg.shared.global [%0], [%1], 16;" :: "r"(d), "l"(s));
}
__device__ __forceinline__ void ldsm4(uint32_t* r, uint32_t addr) {
    asm volatile("ldmatrix.sync.aligned.m8n8.x4.shared.b16 {%0,%1,%2,%3}, [%4];"
        : "=r"(r[0]), "=r"(r[1]), "=r"(r[2]), "=r"(r[3]) : "r"(addr));
}
__device__ __forceinline__ void mma16816(float* c, const uint32_t* a,
                                         uint32_t b0, uint32_t b1) {
    asm volatile(
        "mma.sync.aligned.m16n8k16.row.col.f32.bf16.bf16.f32 "
        "{%0,%1,%2,%3}, {%4,%5,%6,%7}, {%8,%9}, {%0,%1,%2,%3};"
        : "+f"(c[0]), "+f"(c[1]), "+f"(c[2]), "+f"(c[3])
        : "r"(a[0]), "r"(a[1]), "r"(a[2]), "r"(a[3]), "r"(b0), "r"(b1));
}

// ---------------------------------------------------------------------------
// Conversion kernels: fp32 -> (bf16 hi, bf16 lo)
// ---------------------------------------------------------------------------
__device__ __forceinline__ uint32_t pack_bf2(__nv_bfloat16 a, __nv_bfloat16 b) {
    return (uint32_t)__bfloat16_as_ushort(a) | ((uint32_t)__bfloat16_as_ushort(b) << 16);
}
__device__ __forceinline__ void split4(float4 v, uint32_t* hi, uint32_t* lo) {
    float x[4] = {v.x, v.y, v.z, v.w};
    __nv_bfloat16 h[4], l[4];
#pragma unroll
    for (int j = 0; j < 4; j++) {
        h[j] = __float2bfloat16_rn(x[j]);
        l[j] = __float2bfloat16_rn(x[j] - __bfloat162float(h[j]));
    }
    hi[0] = pack_bf2(h[0], h[1]); hi[1] = pack_bf2(h[2], h[3]);
    lo[0] = pack_bf2(l[0], l[1]); lo[1] = pack_bf2(l[2], l[3]);
}
__global__ void cvt_feats_kernel(const float* __restrict__ src) {
    size_t i = (size_t)blockIdx.x * blockDim.x + threadIdx.x;  // float4 index
    float4 v = ((const float4*)src)[i];
    uint32_t hi[2], lo[2];
    split4(v, hi, lo);
    ((uint32_t*)g_fhi)[2 * i]     = hi[0];
    ((uint32_t*)g_fhi)[2 * i + 1] = hi[1];
    ((uint32_t*)g_flo)[2 * i]     = lo[0];
    ((uint32_t*)g_flo)[2 * i + 1] = lo[1];
}
__global__ void cvt_u_kernel(const float* __restrict__ src) {
    size_t i = (size_t)blockIdx.x * blockDim.x + threadIdx.x;
    float4 v = ((const float4*)src)[i];
    uint32_t hi[2], lo[2];
    split4(v, hi, lo);
    ((uint32_t*)g_uhi)[2 * i]     = hi[0];
    ((uint32_t*)g_uhi)[2 * i + 1] = hi[1];
    ((uint32_t*)g_ulo)[2 * i]     = lo[0];
    ((uint32_t*)g_ulo)[2 * i + 1] = lo[1];
}

// ---------------------------------------------------------------------------
// Wh[b,k] = hidden[b,:] . W[k,:]  (fp32, tiny)
// ---------------------------------------------------------------------------
__global__ void wh_kernel(const float* __restrict__ hidden,
                          const float* __restrict__ W) {
    int b = blockIdx.x;
    int k = blockIdx.y * 128 + threadIdx.x;
    __shared__ __align__(16) float4 hs[HIDDEN / 4];
    const float4* hv = (const float4*)(hidden + (size_t)b * HIDDEN);
    for (int i = threadIdx.x; i < HIDDEN / 4; i += 128) hs[i] = hv[i];
    __syncthreads();
    const float4* Wr = (const float4*)(W + (size_t)k * HIDDEN);
    float s = 0.0f;
#pragma unroll 8
    for (int i = 0; i < HIDDEN / 4; i++) {
        float4 a = hs[i], v = Wr[i];
        s += a.x * v.x + a.y * v.y + a.z * v.z + a.w * v.w;
    }
    g_Wh[b * KB + k] = s;
}

// ---------------------------------------------------------------------------
// Energies GEMM via mma.sync bf16 (3-product fp32-emulation) + fused epilogue.
// grid (2, 256): x = N half (col0 = x*256), y = M tile (row0 = y*128).
// 512 threads = 16 warps (4 M x 4 N), warp tile 32x64.
// ---------------------------------------------------------------------------
__global__ __launch_bounds__(512, 1) void energies_mma_kernel(
    const float* __restrict__ bias, const float* __restrict__ wvec) {
    extern __shared__ char smem[];
    const uint32_t sb = smem_to_u32(smem);
    const int tid = threadIdx.x;
    const int lane = tid & 31, warp = tid >> 5;
    const int warp_m = warp & 3, warp_n = warp >> 2;
    const int nhalf = blockIdx.x, mtile = blockIdx.y;
    const int row0 = mtile * BM, col0 = nhalf * BN;
    const int b = row0 >> 9;

    float* whb = (float*)(smem + OFF_WHB);
    float* wv  = (float*)(smem + OFF_WV);
    float* red = (float*)(smem + OFF_RED);

    if (tid < 256) {
        int k = col0 + tid;
        whb[tid] = g_Wh[b * KB + k] + bias[k];
        wv[tid] = wvec[k];
    }

    float acc[2][8][4];
#pragma unroll
    for (int mt = 0; mt < 2; mt++)
#pragma unroll
        for (int nt = 0; nt < 8; nt++)
#pragma unroll
            for (int j = 0; j < 4; j++) acc[mt][nt][j] = 0.0f;

    const __nv_bfloat16* fh = g_fhi + (size_t)row0 * FEAT;
    const __nv_bfloat16* fl = g_flo + (size_t)row0 * FEAT;
    const __nv_bfloat16* uh = g_uhi + (size_t)col0 * FEAT;
    const __nv_bfloat16* ul = g_ulo + (size_t)col0 * FEAT;

    // cp.async destination swizzle:  phys(row, c) = row*64 + ((c ^ ((row>>1)&3))*16)
    const int arow = tid >> 2, ac = tid & 3;
    const uint32_t a_dst = arow * 64 + ((ac ^ ((arow >> 1) & 3)) * 16);
    const int brow0 = tid >> 2, brow1 = brow0 + 128, bc = tid & 3;
    const uint32_t b_dst0 = brow0 * 64 + ((bc ^ ((brow0 >> 1) & 3)) * 16);
    const uint32_t b_dst1 = brow1 * 64 + ((bc ^ ((brow1 >> 1) & 3)) * 16);

    // ldmatrix address components
    const int sub = lane >> 3, l7 = lane & 7;
    const int a_rb = warp_m * 32 + (sub & 1) * 8 + l7;  // + mt*16
    const int a_c0 = sub >> 1;
    const int b_nb = warp_n * 64 + (sub >> 1) * 8 + l7; // + np*16
    const int b_c0 = sub & 1;

#define LOAD_CHUNK(stage, kc) do {                                            \
    uint32_t st_ = sb + (stage) * STAGE_BYTES;                                \
    size_t fo_ = (size_t)(kc) * BK + ac * 8;                                  \
    cpa16(st_ + OFF_AHI + a_dst, fh + (size_t)arow * FEAT + fo_);             \
    cpa16(st_ + OFF_ALO + a_dst, fl + (size_t)arow * FEAT + fo_);             \
    size_t bo_ = (size_t)(kc) * BK + bc * 8;                                  \
    cpa16(st_ + OFF_BHI + b_dst0, uh + (size_t)brow0 * FEAT + bo_);           \
    cpa16(st_ + OFF_BHI + b_dst1, uh + (size_t)brow1 * FEAT + bo_);           \
    cpa16(st_ + OFF_BLO + b_dst0, ul + (size_t)brow0 * FEAT + bo_);           \
    cpa16(st_ + OFF_BLO + b_dst1, ul + (size_t)brow1 * FEAT + bo_);           \
    asm volatile("cp.async.commit_group;" ::: "memory");                      \
} while (0)

    LOAD_CHUNK(0, 0);

    for (int kc = 0; kc < NCHUNK; kc++) {
        const int cur = kc & 1;
        if (kc + 1 < NCHUNK) {
            LOAD_CHUNK(cur ^ 1, kc + 1);
            asm volatile("cp.async.wait_group 1;" ::: "memory");
        } else {
            asm volatile("cp.async.wait_group 0;" ::: "memory");
        }
        __syncthreads();

        const uint32_t st = sb + cur * STAGE_BYTES;
#pragma unroll
        for (int k16 = 0; k16 < 2; k16++) {
            uint32_t ah[2][4], al[2][4];
#pragma unroll
            for (int mt = 0; mt < 2; mt++) {
                int row = a_rb + mt * 16;
                uint32_t aoff = row * 64 + (((k16 * 2 + a_c0) ^ ((row >> 1) & 3)) * 16);
                ldsm4(ah[mt], st + OFF_AHI + aoff);
                ldsm4(al[mt], st + OFF_ALO + aoff);
            }
#pragma unroll
            for (int np = 0; np < 4; np++) {
                int nrow = b_nb + np * 16;
                uint32_t boff = nrow * 64 + (((k16 * 2 + b_c0) ^ ((nrow >> 1) & 3)) * 16);
                uint32_t bh[4], bl[4];
                ldsm4(bh, st + OFF_BHI + boff);
                ldsm4(bl, st + OFF_BLO + boff);
#pragma unroll
                for (int mt = 0; mt < 2; mt++) {
                    mma16816(acc[mt][np * 2 + 0], ah[mt], bh[0], bh[1]);
                    mma16816(acc[mt][np * 2 + 0], ah[mt], bl[0], bl[1]);
                    mma16816(acc[mt][np * 2 + 0], al[mt], bh[0], bh[1]);
                    mma16816(acc[mt][np * 2 + 1], ah[mt], bh[2], bh[3]);
                    mma16816(acc[mt][np * 2 + 1], ah[mt], bl[2], bl[3]);
                    mma16816(acc[mt][np * 2 + 1], al[mt], bh[2], bh[3]);
                }
            }
        }
        __syncthreads();
    }

    // Epilogue: per-thread tanh + w-dot over owned cols, reduce to per-row.
    const int g = lane >> 2, t4 = lane & 3;
#pragma unroll
    for (int mt = 0; mt < 2; mt++) {
#pragma unroll
        for (int half = 0; half < 2; half++) {
            int ml = warp_m * 32 + mt * 16 + half * 8 + g;
            float p = 0.0f;
#pragma unroll
            for (int nt = 0; nt < 8; nt++) {
#pragma unroll
                for (int j = 0; j < 2; j++) {
                    int col = warp_n * 64 + nt * 8 + t4 * 2 + j;
                    p += wv[col] * tanhf(acc[mt][nt][half * 2 + j] + whb[col]);
                }
            }
            p += __shfl_xor_sync(0xffffffffu, p, 1);
            p += __shfl_xor_sync(0xffffffffu, p, 2);
            if (t4 == 0) red[warp_n * 128 + ml] = p;
        }
    }
    __syncthreads();
    if (tid < 128) {
        float s = red[tid] + red[128 + tid] + red[256 + tid] + red[384 + tid];
        g_epart[(size_t)nhalf * BT + row0 + tid] = s;
    }
}

// ---------------------------------------------------------------------------
// Softmax over T per batch (sums the 2 N-half partials)
// ---------------------------------------------------------------------------
__global__ void softmax_kernel(float* __restrict__ wout) {
    int b = blockIdx.x;
    int t = threadIdx.x;
    float e = g_epart[b * TT + t] + g_epart[(size_t)BT + b * TT + t];

    __shared__ float sm[16];
    float m = e;
#pragma unroll
    for (int o = 16; o > 0; o >>= 1) m = fmaxf(m, __shfl_xor_sync(0xffffffffu, m, o));
    if ((t & 31) == 0) sm[t >> 5] = m;
    __syncthreads();
    if (t < 16) {
        float mm = sm[t];
#pragma unroll
        for (int o = 8; o > 0; o >>= 1) mm = fmaxf(mm, __shfl_xor_sync(0xffffu, mm, o));
        if (t == 0) sm[0] = mm;
    }
    __syncthreads();
    m = sm[0];
    __syncthreads();

    float ex = expf(e - m);
    float s = ex;
#pragma unroll
    for (int o = 16; o > 0; o >>= 1) s += __shfl_xor_sync(0xffffffffu, s, o);
    if ((t & 31) == 0) sm[t >> 5] = s;
    __syncthreads();
    if (t < 16) {
        float ss = sm[t];
#pragma unroll
        for (int o = 8; o > 0; o >>= 1) ss += __shfl_xor_sync(0xffffu, ss, o);
        if (t == 0) sm[0] = ss;
    }
    __syncthreads();
    float inv = 1.0f / sm[0];

    float wgt = ex * inv;
    g_weights[b * TT + t] = wgt;
    wout[b * TT + t] = wgt;
}

// ---------------------------------------------------------------------------
// attn_feats[b,f] = sum_t feats[b,t,f] * weights[b,t]   (DRAM-bound)
// ---------------------------------------------------------------------------
__global__ void attn_kernel(const float* __restrict__ feats,
                            float* __restrict__ out) {
    int b = blockIdx.x;
    int f = blockIdx.y * 256 + threadIdx.x;
    __shared__ float ws[TT];
    for (int i = threadIdx.x; i < TT; i += 256) ws[i] = g_weights[b * TT + i];
    __syncthreads();
    const float* fb = feats + (size_t)b * TT * FEAT + f;
    float acc = 0.0f;
#pragma unroll 8
    for (int t = 0; t < TT; t++) acc += fb[(size_t)t * FEAT] * ws[t];
    out[(size_t)b * FEAT + f] = acc;
}

// ---------------------------------------------------------------------------
extern "C" void kernel_launch(void* const* d_in, const int* in_sizes, int n_in,
                              void* d_out, int out_size) {
    const float* hidden = (const float*)d_in[0];  // [64,1024]
    const float* feats  = (const float*)d_in[1];  // [64,512,2048]
    const float* W      = (const float*)d_in[2];  // [512,1024]
    const float* U      = (const float*)d_in[3];  // [512,2048]
    const float* bias   = (const float*)d_in[4];  // [512]
    const float* w      = (const float*)d_in[5];  // [1,512]
    float* out = (float*)d_out;                   // [attn 64*2048 | weights 64*512]

    cudaFuncSetAttribute(energies_mma_kernel,
                         cudaFuncAttributeMaxDynamicSharedMemorySize, SMEM_TOTAL);

    cvt_feats_kernel<<<(BT * (FEAT / 4)) / 256, 256>>>(feats);
    cvt_u_kernel<<<(KB * (FEAT / 4)) / 256, 256>>>(U);
    wh_kernel<<<dim3(64, 4), 128>>>(hidden, W);
    energies_mma_kernel<<<dim3(2, 256), 512, SMEM_TOTAL>>>(bias, w);
    softmax_kernel<<<64, 512>>>(out + (size_t)BATCH * FEAT);
    attn_kernel<<<dim3(64, 8), 256>>>(feats, out);
}